// round 5
// baseline (speedup 1.0000x reference)
#include <cuda_runtime.h>
#include <cuda_bf16.h>

#define NANCH   25200
#define NCLS    80
#define NB      16
#define TOPK    128
#define MAXOUT  100
#define CAP     4096
#define SCORE_THR 0.25f
#define IOU_THR   0.45f

// ---------------- static device scratch (no allocations) ----------------
__device__ float  g_scores[(size_t)NB * NCLS * NANCH];   // [b][c][a]  (129 MB)
__device__ float4 g_boxes [(size_t)NB * NANCH];          // [b][a]
__device__ float  g_cand_s[(size_t)NB * NCLS * MAXOUT];  // [b][c][r]
__device__ float4 g_cand_b[(size_t)NB * NCLS * MAXOUT];

// sigmoid: deterministic intrinsics (immune to fast-math variation)
__device__ __forceinline__ float sigm(float x) {
    return __fdividef(1.0f, __fadd_rn(1.0f, __expf(-x)));
}

// ---------------- block-wide bitonic sort, descending, 64-bit keys ----------------
__device__ void bitonic_desc(unsigned long long* a, int n) {
    for (int k = 2; k <= n; k <<= 1) {
        for (int j = k >> 1; j > 0; j >>= 1) {
            __syncthreads();
            for (int i = threadIdx.x; i < n; i += blockDim.x) {
                int ixj = i ^ j;
                if (ixj > i) {
                    unsigned long long va = a[i], vb = a[ixj];
                    bool doswap = ((i & k) == 0) ? (va < vb) : (va > vb);
                    if (doswap) { a[i] = vb; a[ixj] = va; }
                }
            }
        }
    }
    __syncthreads();
}

// ---------------- stage 1: decode one pyramid level ----------------
// grid: (ceil(nCells/32), NB), block: 256 threads. Each block: 32 cells (96 anchors).
__global__ void decode_kernel(const float* __restrict__ in, int W, int nCells,
                              float stride,
                              float aw0, float ah0, float aw1, float ah1,
                              float aw2, float ah2, int aOff)
{
    __shared__ float tile[32 * 255];
    __shared__ float objs[96];
    int b = blockIdx.y;
    int cell0 = blockIdx.x * 32;
    int nC = nCells - cell0; if (nC > 32) nC = 32;
    const float* src = in + ((size_t)b * nCells + cell0) * 255;
    int tid = threadIdx.x;
    int tot = nC * 255;
    for (int i = tid; i < tot; i += 256) tile[i] = src[i];
    __syncthreads();

    int nA = nC * 3;
    if (tid < nA) {
        int cl = tid / 3, k = tid - cl * 3;
        const float* p = tile + cl * 255 + k * 85;
        int cell = cell0 + cl;
        int h = cell / W, w = cell - h * W;
        float cx = __fmul_rn(__fadd_rn(sigm(p[0]), (float)w), stride);
        float cy = __fmul_rn(__fadd_rn(sigm(p[1]), (float)h), stride);
        float aw = (k == 0) ? aw0 : ((k == 1) ? aw1 : aw2);
        float ah = (k == 0) ? ah0 : ((k == 1) ? ah1 : ah2);
        float ww = __fmul_rn(__expf(p[2]), aw);
        float hh = __fmul_rn(__expf(p[3]), ah);
        float hwd = __fmul_rn(ww, 0.5f), hhd = __fmul_rn(hh, 0.5f);
        float4 bo = make_float4(__fsub_rn(cx, hwd), __fsub_rn(cy, hhd),
                                __fadd_rn(cx, hwd), __fadd_rn(cy, hhd));
        g_boxes[(size_t)b * NANCH + aOff + cell * 3 + k] = bo;
        objs[tid] = sigm(p[4]);
    }
    __syncthreads();

    float* sOut = g_scores + (size_t)b * NCLS * NANCH + (aOff + cell0 * 3);
    int total = nA * NCLS;
    if (nA == 96) {
        for (int e = tid; e < total; e += 256) {
            int c = e / 96, al = e - c * 96;
            int cl = al / 3, k = al - cl * 3;
            float v = __fmul_rn(objs[al], sigm(tile[cl * 255 + k * 85 + 5 + c]));
            sOut[(size_t)c * NANCH + al] = v;
        }
    } else {
        for (int e = tid; e < total; e += 256) {
            int c = e / nA, al = e - c * nA;
            int cl = al / 3, k = al - cl * 3;
            float v = __fmul_rn(objs[al], sigm(tile[cl * 255 + k * 85 + 5 + c]));
            sOut[(size_t)c * NANCH + al] = v;
        }
    }
}

// ---------------- stage 2: per (image, class) top-128 + NMS + top-100 ----------------
// grid: NB*NCLS blocks, 256 threads
__global__ void nms_kernel()
{
    __shared__ int hist[272];
    __shared__ unsigned long long list[CAP];
    __shared__ int s_cnt, s_B;
    __shared__ float4 sBox[TOPK];
    __shared__ float  sArea[TOPK];
    __shared__ float  sScore[TOPK];
    __shared__ unsigned sSup[TOPK][4];
    __shared__ unsigned s_keep[4];

    int flat = blockIdx.x;
    int b = flat / NCLS;
    int tid = threadIdx.x;
    const float4* row4 = (const float4*)(g_scores + (size_t)flat * NANCH);

    for (int i = tid; i < 272; i += 256) hist[i] = 0;
    if (tid == 0) s_cnt = 0;
    __syncthreads();

    // pass 1: histogram of (bits>>16); scores in (0.25,1) -> 257 buckets
    for (int i = tid; i < NANCH / 4; i += 256) {
        float4 v = row4[i];
        float vs[4] = {v.x, v.y, v.z, v.w};
        #pragma unroll
        for (int l = 0; l < 4; l++) {
            if (vs[l] > SCORE_THR) {
                int h = (int)(__float_as_uint(vs[l]) >> 16) - 0x3E80;
                h = max(0, min(256, h));
                atomicAdd(&hist[h], 1);
            }
        }
    }
    __syncthreads();
    if (tid == 0) {
        int acc = 0, Bq = -1;
        for (int h = 256; h >= 0; h--) { acc += hist[h]; if (acc >= TOPK) { Bq = h; break; } }
        s_B = Bq;
    }
    __syncthreads();
    unsigned cutHi = (s_B < 0) ? 1u : ((unsigned)(s_B + 0x3E80) << 16);

    // pass 2: collect superset of the top-128 (all keys above the bucket cut)
    for (int i = tid; i < NANCH / 4; i += 256) {
        float4 v = row4[i];
        float vs[4] = {v.x, v.y, v.z, v.w};
        #pragma unroll
        for (int l = 0; l < 4; l++) {
            unsigned bits = __float_as_uint(vs[l]);
            if (vs[l] > SCORE_THR && bits >= cutHi) {
                int p = atomicAdd(&s_cnt, 1);
                if (p < CAP)
                    list[p] = ((unsigned long long)bits << 32) | (~(unsigned)(4 * i + l));
            }
        }
    }
    __syncthreads();
    int M = min(s_cnt, CAP);
    int M2 = TOPK; while (M2 < M) M2 <<= 1;
    for (int i = tid; i < M2; i += 256) if (i >= M) list[i] = 0ull;
    bitonic_desc(list, M2);   // top-128 exact & stable (ties -> lower index)

    if (tid < TOPK) {
        unsigned long long k = list[tid];
        unsigned hi = (unsigned)(k >> 32);
        unsigned idx = ~((unsigned)(k & 0xFFFFFFFFull));
        if (hi == 0u) idx = 0;   // padding slot: score -1, never active/output
        float4 bx = g_boxes[(size_t)b * NANCH + idx];
        sBox[tid] = bx;
        sArea[tid] = __fmul_rn(__fsub_rn(bx.z, bx.x), __fsub_rn(bx.w, bx.y));
        sScore[tid] = hi ? __uint_as_float(hi) : -1.0f;
    }
    __syncthreads();

    // suppression bitmask matrix: sup[i][j] for j > i
    for (int t = tid; t < TOPK * 4; t += 256) {
        int i = t >> 2, w = t & 3;
        float4 bi = sBox[i]; float ai = sArea[i];
        unsigned m = 0;
        for (int jj = 0; jj < 32; jj++) {
            int j = w * 32 + jj;
            if (j > i) {
                float4 bj = sBox[j];
                float w0 = fmaxf(__fsub_rn(fminf(bi.z, bj.z), fmaxf(bi.x, bj.x)), 0.0f);
                float h0 = fmaxf(__fsub_rn(fminf(bi.w, bj.w), fmaxf(bi.y, bj.y)), 0.0f);
                float inter = __fmul_rn(w0, h0);
                float den = __fadd_rn(__fsub_rn(__fadd_rn(ai, sArea[j]), inter), 1e-9f);
                float iou = __fdiv_rn(inter, den);
                if (iou > IOU_THR) m |= (1u << jj);
            }
        }
        sSup[i][w] = m;
    }
    __syncthreads();

    // greedy NMS — exact reference scan, serial on thread 0 over bitmasks
    if (tid == 0) {
        unsigned k0 = ~0u, k1 = ~0u, k2 = ~0u, k3 = ~0u;
        for (int i = 0; i < TOPK; i++) {
            unsigned kw = (i < 32) ? k0 : ((i < 64) ? k1 : ((i < 96) ? k2 : k3));
            if (((kw >> (i & 31)) & 1u) && sScore[i] > 0.0f) {
                k0 &= ~sSup[i][0]; k1 &= ~sSup[i][1];
                k2 &= ~sSup[i][2]; k3 &= ~sSup[i][3];
            }
        }
        s_keep[0] = k0; s_keep[1] = k1; s_keep[2] = k2; s_keep[3] = k3;
    }
    __syncthreads();

    // stable top-100 of masked scores (ss = valid ? s : -1)
    if (tid < TOPK) {
        bool valid = ((s_keep[tid >> 5] >> (tid & 31)) & 1u) && (sScore[tid] > 0.0f);
        unsigned hi = valid ? __float_as_uint(sScore[tid]) : 0u;
        list[tid] = ((unsigned long long)hi << 32) | (unsigned)(TOPK - 1 - tid);
    }
    bitonic_desc(list, TOPK);
    if (tid < MAXOUT) {
        unsigned long long k = list[tid];
        unsigned hi = (unsigned)(k >> 32);
        int slot = TOPK - 1 - (int)(k & 0xFFFFFFFFull);
        g_cand_s[(size_t)flat * MAXOUT + tid] = hi ? __uint_as_float(hi) : -1.0f;
        g_cand_b[(size_t)flat * MAXOUT + tid] = sBox[slot];
    }
}

// ---------------- stage 3: per-image merge (top-100 of 8000, class-major tiebreak) ----------------
__global__ void merge_kernel(float* __restrict__ out)
{
    __shared__ int hist[272];
    __shared__ unsigned long long list[CAP];
    __shared__ int s_cnt, s_B, s_nv;
    int b = blockIdx.x, tid = threadIdx.x;
    const float* cs = g_cand_s + (size_t)b * NCLS * MAXOUT;

    for (int i = tid; i < 272; i += 256) hist[i] = 0;
    if (tid == 0) { s_cnt = 0; s_nv = 0; }
    __syncthreads();

    for (int f = tid; f < NCLS * MAXOUT; f += 256) {
        float v = cs[f];
        if (v > 0.0f) {
            int h = (int)(__float_as_uint(v) >> 16) - 0x3E80;
            h = max(0, min(256, h));
            atomicAdd(&hist[h], 1);
        }
    }
    __syncthreads();
    if (tid == 0) {
        int acc = 0, Bq = -1;
        for (int h = 256; h >= 0; h--) { acc += hist[h]; if (acc >= MAXOUT) { Bq = h; break; } }
        s_B = Bq;
    }
    __syncthreads();
    unsigned cutHi = (s_B < 0) ? 1u : ((unsigned)(s_B + 0x3E80) << 16);

    for (int f = tid; f < NCLS * MAXOUT; f += 256) {
        float v = cs[f];
        unsigned bits = __float_as_uint(v);
        if (v > 0.0f && bits >= cutHi) {
            int p = atomicAdd(&s_cnt, 1);
            if (p < CAP)
                list[p] = ((unsigned long long)bits << 32) | (unsigned)(8191 - f);
        }
    }
    __syncthreads();
    int M = min(s_cnt, CAP);
    int M2 = TOPK; while (M2 < M) M2 <<= 1;
    for (int i = tid; i < M2; i += 256) if (i >= M) list[i] = 0ull;
    bitonic_desc(list, M2);

    if (tid < MAXOUT) {
        unsigned long long k = list[tid];
        unsigned hi = (unsigned)(k >> 32);
        int f = 8191 - (int)(k & 0xFFFFFFFFull);
        bool valid = (hi != 0u) && (f >= 0) && (f < NCLS * MAXOUT);
        float sc = valid ? __uint_as_float(hi) : 0.0f;
        float4 bx = valid ? g_cand_b[(size_t)b * NCLS * MAXOUT + f]
                          : make_float4(0.f, 0.f, 0.f, 0.f);
        float cls = valid ? (float)(f / MAXOUT) : 0.0f;
        int r = b * MAXOUT + tid;
        out[r * 4 + 0] = bx.x; out[r * 4 + 1] = bx.y;
        out[r * 4 + 2] = bx.z; out[r * 4 + 3] = bx.w;
        out[NB * MAXOUT * 4 + r] = sc;    // scores block
        out[NB * MAXOUT * 5 + r] = cls;   // class-id block
        if (valid) atomicAdd(&s_nv, 1);
    }
    __syncthreads();
    if (tid == 0) out[NB * MAXOUT * 6 + b] = (float)s_nv;  // n_valid block
}

// ---------------- launcher ----------------
extern "C" void kernel_launch(void* const* d_in, const int* in_sizes, int n_in,
                              void* d_out, int out_size)
{
    const float* p3 = (const float*)d_in[0];
    const float* p4 = (const float*)d_in[1];
    const float* p5 = (const float*)d_in[2];
    float* out = (float*)d_out;

    decode_kernel<<<dim3(200, NB), 256>>>(p3, 80, 6400,  8.0f,
                                          10.f, 13.f, 16.f, 30.f, 33.f, 23.f, 0);
    decode_kernel<<<dim3(50,  NB), 256>>>(p4, 40, 1600, 16.0f,
                                          30.f, 61.f, 62.f, 45.f, 59.f, 119.f, 19200);
    decode_kernel<<<dim3(13,  NB), 256>>>(p5, 20,  400, 32.0f,
                                          116.f, 90.f, 156.f, 198.f, 373.f, 326.f, 24000);
    nms_kernel<<<NB * NCLS, 256>>>();
    merge_kernel<<<NB, 256>>>(out);
}